// round 16
// baseline (speedup 1.0000x reference)
#include <cuda_runtime.h>
#include <cuda_fp16.h>
#include <mma.h>

using namespace nvcuda;

#define NN 100000
#define EE 800000
#define HID 128
#define NB_SCAN 98   // ceil(NN/1024)

// ---------------- scratch (static device globals; no allocation) -------------
__device__ int    g_cnt[NN];
__device__ int    g_rowptr[NN + 1];
__device__ int    g_wptr[NN];
__device__ float  g_dinv[NN];
__device__ int    g_colsrc[EE];
__device__ float  g_h0[NN * 16];
__device__ float  g_h0s[NN * 16];     // h0 * dinv (pre-scaled for gather)
__device__ float  g_agg16v[NN * 16];  // layer-0 aggregation output
__device__ __half g_aggh[NN * HID];   // aggregation output (fp16, GEMM A input)
__device__ __half g_hs[NN * HID];     // relu(h)*dinv inter-layer buffer (fp16)
__device__ int    g_bsum[128];
__device__ int    g_bsumx[128];
__device__ __half g_wh[5 * 128 * 128];  // Wh[0..3], Wr1 in fp16

// ---------------- graph preprocessing ----------------------------------------

// fused: zero counts + build h0 + convert weights to fp16
// NOTE: grid must cover max(NN, 5*128*128) threads.
__global__ void k_initw(const float* __restrict__ x, const float* __restrict__ xm,
                        const float* __restrict__ Wh, const float* __restrict__ Wr1) {
    int i = blockIdx.x * blockDim.x + threadIdx.x;
    if (i < NN) {
        g_cnt[i] = 0;
#pragma unroll
        for (int c = 0; c < 8; c++) {
            g_h0[i * 16 + c]     = x[i * 10 + c];
            g_h0[i * 16 + 8 + c] = xm[i * 10 + c];
        }
    }
    if (i < 5 * 128 * 128) {
        float v = (i < 4 * 128 * 128) ? Wh[i] : Wr1[i - 4 * 128 * 128];
        g_wh[i] = __float2half(v);
    }
}

__global__ void k_count(const int* __restrict__ ei) {
    int e = blockIdx.x * blockDim.x + threadIdx.x;
    if (e < EE) atomicAdd(&g_cnt[ei[EE + e]], 1);
}

// pass 1: per-block exclusive scan; also compute dinv
__global__ void k_scan1() {
    __shared__ int sdata[1024];
    int t = threadIdx.x;
    int i = blockIdx.x * 1024 + t;
    int v = (i < NN) ? g_cnt[i] : 0;
    if (i < NN) g_dinv[i] = rsqrtf((float)v + 1.0f);
    sdata[t] = v;
    __syncthreads();
#pragma unroll
    for (int off = 1; off < 1024; off <<= 1) {
        int x = (t >= off) ? sdata[t - off] : 0;
        __syncthreads();
        sdata[t] += x;
        __syncthreads();
    }
    if (i < NN) {
        int excl = sdata[t] - v;
        g_rowptr[i] = excl;
        g_wptr[i]   = excl;
    }
    if (t == 1023) g_bsum[blockIdx.x] = sdata[1023];
}

// pass 2: scan the 98 block sums
__global__ void k_scan2() {
    __shared__ int sdata[128];
    int t = threadIdx.x;
    int v = (t < NB_SCAN) ? g_bsum[t] : 0;
    sdata[t] = v;
    __syncthreads();
#pragma unroll
    for (int off = 1; off < 128; off <<= 1) {
        int x = (t >= off) ? sdata[t - off] : 0;
        __syncthreads();
        sdata[t] += x;
        __syncthreads();
    }
    if (t < NB_SCAN) g_bsumx[t] = sdata[t] - v;
}

// pass 3: add block offsets; also build h0s = h0 * dinv
__global__ void k_scan3() {
    int i = blockIdx.x * blockDim.x + threadIdx.x;
    if (i < NN) {
        int off = g_bsumx[i >> 10];
        g_rowptr[i] += off;
        g_wptr[i]   += off;
        float dv = g_dinv[i];
#pragma unroll
        for (int c = 0; c < 16; c++)
            g_h0s[i * 16 + c] = g_h0[i * 16 + c] * dv;
    }
    if (i == 0) g_rowptr[NN] = EE;
}

__global__ void k_fill(const int* __restrict__ ei) {
    int e = blockIdx.x * blockDim.x + threadIdx.x;
    if (e < EE) {
        int s = ei[e];
        int d = ei[EE + e];
        int p = atomicAdd(&g_wptr[d], 1);
        g_colsrc[p] = s;
    }
}

// ---------------- aggregation (gather over CSR, pre-scaled inputs) ------------

// layer-0: 4 lanes per node (float4 each = 16 floats/row), unroll 4 + tail.
__global__ void k_agg16() {
    int tid = blockIdx.x * blockDim.x + threadIdx.x;
    int v = tid >> 2;
    int q = tid & 3;
    if (v >= NN) return;
    const float4* hp = (const float4*)g_h0s;   // 4 float4 per row
    float dv = g_dinv[v];
    float4 s = __ldg(hp + v * 4 + q);
    float a0 = s.x, a1 = s.y, a2 = s.z, a3 = s.w;
    int e = g_rowptr[v], end = g_rowptr[v + 1];
    for (; e + 4 <= end; e += 4) {
        int u0 = g_colsrc[e + 0];
        int u1 = g_colsrc[e + 1];
        int u2 = g_colsrc[e + 2];
        int u3 = g_colsrc[e + 3];
        float4 x0 = __ldg(hp + u0 * 4 + q);
        float4 x1 = __ldg(hp + u1 * 4 + q);
        float4 x2 = __ldg(hp + u2 * 4 + q);
        float4 x3 = __ldg(hp + u3 * 4 + q);
        a0 += (x0.x + x1.x) + (x2.x + x3.x);
        a1 += (x0.y + x1.y) + (x2.y + x3.y);
        a2 += (x0.z + x1.z) + (x2.z + x3.z);
        a3 += (x0.w + x1.w) + (x2.w + x3.w);
    }
    for (; e < end; e++) {
        int u = g_colsrc[e];
        float4 x = __ldg(hp + u * 4 + q);
        a0 += x.x; a1 += x.y; a2 += x.z; a3 += x.w;
    }
    float4 r = make_float4(a0 * dv, a1 * dv, a2 * dv, a3 * dv);
    *((float4*)g_agg16v + v * 4 + q) = r;
}

__device__ __forceinline__ void acc8(float* a, uint4 r) {
    float2 p0 = __half22float2(*(const __half2*)&r.x);
    float2 p1 = __half22float2(*(const __half2*)&r.y);
    float2 p2 = __half22float2(*(const __half2*)&r.z);
    float2 p3 = __half22float2(*(const __half2*)&r.w);
    a[0] += p0.x; a[1] += p0.y; a[2] += p1.x; a[3] += p1.y;
    a[4] += p2.x; a[5] += p2.y; a[6] += p3.x; a[7] += p3.y;
}

// 128-channel: 16 lanes per node (2 nodes/warp), uint4 = 8 halves per lane.
__global__ void __launch_bounds__(256) k_agg128() {
    int tid = blockIdx.x * blockDim.x + threadIdx.x;
    int node = tid >> 4;
    if (node >= NN) return;
    int lane = threadIdx.x & 15;
    const uint4* hp = (const uint4*)g_hs;   // 16 uint4 per 128-half row
    float dv = g_dinv[node];
    float a[8] = {0.f, 0.f, 0.f, 0.f, 0.f, 0.f, 0.f, 0.f};
    acc8(a, __ldg(hp + node * 16 + lane));  // self term
    int e = g_rowptr[node], end = g_rowptr[node + 1];
    for (; e + 4 <= end; e += 4) {
        int u0 = g_colsrc[e + 0];
        int u1 = g_colsrc[e + 1];
        int u2 = g_colsrc[e + 2];
        int u3 = g_colsrc[e + 3];
        uint4 r0 = __ldg(hp + u0 * 16 + lane);
        uint4 r1 = __ldg(hp + u1 * 16 + lane);
        uint4 r2 = __ldg(hp + u2 * 16 + lane);
        uint4 r3 = __ldg(hp + u3 * 16 + lane);
        acc8(a, r0); acc8(a, r1); acc8(a, r2); acc8(a, r3);
    }
    for (; e < end; e++) {
        int u = g_colsrc[e];
        acc8(a, __ldg(hp + u * 16 + lane));
    }
    __half2 h0 = __floats2half2_rn(a[0] * dv, a[1] * dv);
    __half2 h1 = __floats2half2_rn(a[2] * dv, a[3] * dv);
    __half2 h2 = __floats2half2_rn(a[4] * dv, a[5] * dv);
    __half2 h3 = __floats2half2_rn(a[6] * dv, a[7] * dv);
    uint4 ov;
    ov.x = *(const unsigned int*)&h0;
    ov.y = *(const unsigned int*)&h1;
    ov.z = *(const unsigned int*)&h2;
    ov.w = *(const unsigned int*)&h3;
    *((uint4*)g_aggh + node * 16 + lane) = ov;
}

// ---------------- GEMMs -------------------------------------------------------

// layer-0 GEMM: [N,16] @ [16,128] + b -> hs(fp16) = relu(out)*dinv
__global__ void k_gemm0(const float* __restrict__ W0, const float* __restrict__ b0) {
    __shared__ float Ws[16 * 128];
    int t = threadIdx.x;
    for (int i = t; i < 16 * 128; i += 256) Ws[i] = W0[i];
    __syncthreads();
    int row = blockIdx.x * 2 + (t >> 7);
    int col = t & 127;
    float acc = b0[col];
#pragma unroll
    for (int k = 0; k < 16; k++)
        acc += g_agg16v[row * 16 + k] * Ws[k * 128 + col];
    g_hs[row * HID + col] = __float2half(fmaxf(acc, 0.f) * g_dinv[row]);
}

// W-resident 2-tile fp16 tensor-core GEMM: each block keeps the full 128x128 W
// in smem (loaded once) and processes TWO 128-row tiles. Inner MMA loop has no
// syncs (both operands resident).
// emode: 0 = raw fp32 out, 2 = relu*dinv -> fp16 hs buffer,
//        3 = fused head (t=relu(.) in smem, pred = t@Wr2 + br2)
#define H_LD 136
#define H_SMEM (128 * H_LD * 2 + 128 * H_LD * 2 + 8 * 256 * 4 + 128 * 3 * 4)

__global__ void __launch_bounds__(256)
k_gemm16(const __half* __restrict__ in_h, const float* __restrict__ in_f,
         int widx, const float* __restrict__ bias,
         float* __restrict__ out_f, __half* __restrict__ out_h, int emode,
         const float* __restrict__ Wr2, const float* __restrict__ br2,
         float* __restrict__ out_pred) {
    extern __shared__ char sraw[];
    __half* Wsm = (__half*)sraw;                // 128 x H_LD (full W, resident)
    __half* As  = Wsm + 128 * H_LD;             // 128 x H_LD
    float* scratch = (float*)(As + 128 * H_LD); // 8 x 256
    float* wr2s = scratch + 8 * 256;            // 128 x 3

    int t = threadIdx.x;
    int warp = t >> 5;
    int lane = t & 31;
    int warp_r = warp & 3;
    int warp_c = warp >> 2;

    const __half* W = g_wh + widx * 128 * 128;

    // ---- load full W once (2048 uint4, 8 per thread) ----
#pragma unroll
    for (int l = 0; l < 8; l++) {
        int idx = t + l * 256;
        int kr = idx >> 4, q = idx & 15;
        *(uint4*)(&Wsm[kr * H_LD + q * 8]) = __ldg((const uint4*)(W + kr * 128 + q * 8));
    }
    if (emode == 3) {
        for (int i = t; i < 384; i += 256) wr2s[i] = __ldg(&Wr2[i]);
    }

#pragma unroll 1
    for (int tile = 0; tile < 2; tile++) {
        int row0 = (blockIdx.x * 2 + tile) * 128;
        bool full = (row0 + 128 <= NN);
        if (tile) __syncthreads();   // previous tile's As reads complete

        // ---- load A tile (128 x 128 halves) ----
        if (in_h) {
#pragma unroll
            for (int l = 0; l < 8; l++) {
                int idx = t + l * 256;
                int r = idx >> 4, q = idx & 15;
                int gr = row0 + r;
                uint4 v = make_uint4(0, 0, 0, 0);
                if (gr < NN) v = __ldg((const uint4*)(in_h + gr * HID + q * 8));
                *(uint4*)(&As[r * H_LD + q * 8]) = v;
            }
        } else {
            // fp32 input with relu (head path)
#pragma unroll
            for (int l = 0; l < 16; l++) {
                int idx = t + l * 256;
                int r = idx >> 5, q = idx & 31;
                int gr = row0 + r;
                float4 v = make_float4(0.f, 0.f, 0.f, 0.f);
                if (gr < NN) v = __ldg((const float4*)(in_f + gr * HID + q * 4));
                __half2 p0 = __floats2half2_rn(fmaxf(v.x, 0.f), fmaxf(v.y, 0.f));
                __half2 p1 = __floats2half2_rn(fmaxf(v.z, 0.f), fmaxf(v.w, 0.f));
                *(__half2*)(&As[r * H_LD + q * 4])     = p0;
                *(__half2*)(&As[r * H_LD + q * 4 + 2]) = p1;
            }
        }
        __syncthreads();

        // ---- MMA: 8 k-steps, zero syncs (operands resident) ----
        wmma::fragment<wmma::accumulator, 16, 16, 16, float> acc[2][4];
#pragma unroll
        for (int i = 0; i < 2; i++)
#pragma unroll
            for (int j = 0; j < 4; j++) wmma::fill_fragment(acc[i][j], 0.0f);

#pragma unroll
        for (int ks = 0; ks < 8; ks++) {
            int ka = ks * 16;
            wmma::fragment<wmma::matrix_a, 16, 16, 16, __half, wmma::row_major> af[2];
            wmma::fragment<wmma::matrix_b, 16, 16, 16, __half, wmma::row_major> bf[4];
#pragma unroll
            for (int i = 0; i < 2; i++)
                wmma::load_matrix_sync(af[i], &As[(warp_r * 32 + i * 16) * H_LD + ka], H_LD);
#pragma unroll
            for (int j = 0; j < 4; j++)
                wmma::load_matrix_sync(bf[j], &Wsm[ka * H_LD + warp_c * 64 + j * 16], H_LD);
#pragma unroll
            for (int i = 0; i < 2; i++)
#pragma unroll
                for (int j = 0; j < 4; j++)
                    wmma::mma_sync(acc[i][j], af[i], bf[j], acc[i][j]);
        }

        if (emode == 3) __syncthreads();  // all As reads done before t writes

        // ---- epilogue ----
        float* sc = &scratch[warp * 256];
#pragma unroll
        for (int i = 0; i < 2; i++)
#pragma unroll
            for (int j = 0; j < 4; j++) {
                wmma::store_matrix_sync(sc, acc[i][j], 16, wmma::mem_row_major);
                __syncwarp();
#pragma unroll
                for (int e = 0; e < 8; e++) {
                    int idx = lane + e * 32;
                    int r = idx >> 4, c = idx & 15;
                    int rl = warp_r * 32 + i * 16 + r;
                    int gr = row0 + rl;
                    int gc = warp_c * 64 + j * 16 + c;
                    if (full || gr < NN) {
                        float v = sc[idx] + __ldg(&bias[gc]);
                        if (emode == 2) {
                            v = fmaxf(v, 0.f) * __ldg(&g_dinv[gr]);
                            out_h[gr * HID + gc] = __float2half(v);
                        } else if (emode == 3) {
                            As[rl * H_LD + gc] = __float2half(fmaxf(v, 0.f));
                        } else {
                            out_f[gr * HID + gc] = v;
                        }
                    }
                }
                __syncwarp();
            }

        // ---- fused pred head (emode 3): pred = t @ Wr2 + br2 ----
        if (emode == 3) {
            __syncthreads();  // t tile complete in As
            int row = t >> 1;
            int half_id = t & 1;
            int k0 = half_id * 64;
            float p0 = 0.f, p1 = 0.f, p2 = 0.f;
#pragma unroll
            for (int k = 0; k < 64; k += 2) {
                __half2 hv = *(__half2*)(&As[row * H_LD + k0 + k]);
                float2 f = __half22float2(hv);
                const float* w0 = &wr2s[(k0 + k) * 3];
                p0 += f.x * w0[0] + f.y * w0[3];
                p1 += f.x * w0[1] + f.y * w0[4];
                p2 += f.x * w0[2] + f.y * w0[5];
            }
            p0 += __shfl_xor_sync(0xFFFFFFFF, p0, 1);
            p1 += __shfl_xor_sync(0xFFFFFFFF, p1, 1);
            p2 += __shfl_xor_sync(0xFFFFFFFF, p2, 1);
            int gr = row0 + row;
            if (half_id == 0 && gr < NN) {
                out_pred[gr * 3 + 0] = p0 + __ldg(&br2[0]);
                out_pred[gr * 3 + 1] = p1 + __ldg(&br2[1]);
                out_pred[gr * 3 + 2] = p2 + __ldg(&br2[2]);
            }
        }
    }
}

// ---------------- launch ------------------------------------------------------

extern "C" void kernel_launch(void* const* d_in, const int* in_sizes, int n_in,
                              void* d_out, int out_size) {
    const float* x    = (const float*)d_in[0];
    const float* xm   = (const float*)d_in[1];
    const int*   ei   = (const int*)d_in[2];
    const float* W0   = (const float*)d_in[3];
    const float* b0   = (const float*)d_in[4];
    const float* Wh   = (const float*)d_in[5];
    const float* bh   = (const float*)d_in[6];
    const float* Wr1  = (const float*)d_in[7];
    const float* br1  = (const float*)d_in[8];
    const float* Wr2  = (const float*)d_in[9];
    const float* br2  = (const float*)d_in[10];
    float* out = (float*)d_out;
    float* out_emb  = out;             // [N,128]
    float* out_pred = out + NN * HID;  // [N,3]

    __half* p_aggh; cudaGetSymbolAddress((void**)&p_aggh, g_aggh);
    __half* p_hs;   cudaGetSymbolAddress((void**)&p_hs,   g_hs);

    static int smem_set = 0;
    if (!smem_set) {
        cudaFuncSetAttribute(k_gemm16, cudaFuncAttributeMaxDynamicSharedMemorySize,
                             H_SMEM);
        smem_set = 1;
    }

    // graph preprocessing (init + weight conversion fused); grid covers
    // max(NN, 5*128*128) — all NN node clears required for graph replay.
    int initw_threads = (NN > 5 * 128 * 128) ? NN : 5 * 128 * 128;
    k_initw<<<(initw_threads + 255) / 256, 256>>>(x, xm, Wh, Wr1);
    k_count<<<(EE + 255) / 256, 256>>>(ei);
    k_scan1<<<NB_SCAN, 1024>>>();
    k_scan2<<<1, 128>>>();
    k_scan3<<<(NN + 255) / 256, 256>>>();
    k_fill<<<(EE + 255) / 256, 256>>>(ei);

    // 782 row-tiles of 128; each block handles 2 -> 391 blocks
    int gemm_blocks = (NN + 255) / 256;

    // layer 0: aggregate 16-dim (4 lanes/node), then GEMM to 128
    k_agg16<<<(NN * 4 + 255) / 256, 256>>>();
    k_gemm0<<<NN / 2, 256>>>(W0, b0);

    // hidden layers 0..3
    for (int i = 0; i < 4; i++) {
        k_agg128<<<(NN * 16 + 255) / 256, 256>>>();
        if (i == 3)
            k_gemm16<<<gemm_blocks, 256, H_SMEM>>>(p_aggh, nullptr, i, bh + i * 128,
                                                   out_emb, nullptr, 0,
                                                   nullptr, nullptr, nullptr);
        else
            k_gemm16<<<gemm_blocks, 256, H_SMEM>>>(p_aggh, nullptr, i, bh + i * 128,
                                                   nullptr, p_hs, 2,
                                                   nullptr, nullptr, nullptr);
    }

    // fused head: t = relu(relu(emb) @ Wr1 + br1); pred = t @ Wr2 + br2
    k_gemm16<<<gemm_blocks, 256, H_SMEM>>>(nullptr, out_emb, 4, br1,
                                           nullptr, nullptr, 3,
                                           Wr2, br2, out_pred);
}

// round 17
// speedup vs baseline: 1.2112x; 1.2112x over previous
#include <cuda_runtime.h>
#include <cuda_fp16.h>
#include <mma.h>

using namespace nvcuda;

#define NN 100000
#define EE 800000
#define HID 128
#define NB_SCAN 98   // ceil(NN/1024)

// ---------------- scratch (static device globals; no allocation) -------------
__device__ int    g_cnt[NN];
__device__ int    g_rowptr[NN + 1];
__device__ int    g_wptr[NN];
__device__ float  g_dinv[NN];
__device__ int    g_colsrc[EE];
__device__ float  g_h0[NN * 16];
__device__ float  g_h0s[NN * 16];     // h0 * dinv (pre-scaled for gather)
__device__ float  g_agg16v[NN * 16];  // layer-0 aggregation output
__device__ __half g_aggh[NN * HID];   // aggregation output (fp16, GEMM A input)
__device__ __half g_hs[NN * HID];     // relu(h)*dinv inter-layer buffer (fp16)
__device__ int    g_bsum[128];
__device__ __half g_wh[5 * 128 * 128];  // Wh[0..3], Wr1 in fp16

// ---------------- graph preprocessing ----------------------------------------

// fused: zero counts + build h0 + convert weights to fp16
// NOTE: grid must cover max(NN, 5*128*128) threads.
__global__ void k_initw(const float* __restrict__ x, const float* __restrict__ xm,
                        const float* __restrict__ Wh, const float* __restrict__ Wr1) {
    int i = blockIdx.x * blockDim.x + threadIdx.x;
    if (i < NN) {
        g_cnt[i] = 0;
#pragma unroll
        for (int c = 0; c < 8; c++) {
            g_h0[i * 16 + c]     = x[i * 10 + c];
            g_h0[i * 16 + 8 + c] = xm[i * 10 + c];
        }
    }
    if (i < 5 * 128 * 128) {
        float v = (i < 4 * 128 * 128) ? Wh[i] : Wr1[i - 4 * 128 * 128];
        g_wh[i] = __float2half(v);
    }
}

__global__ void k_count(const int* __restrict__ ei) {
    int e = blockIdx.x * blockDim.x + threadIdx.x;
    if (e < EE) atomicAdd(&g_cnt[ei[EE + e]], 1);
}

// pass 1: per-block exclusive scan; also compute dinv
__global__ void k_scan1() {
    __shared__ int sdata[1024];
    int t = threadIdx.x;
    int i = blockIdx.x * 1024 + t;
    int v = (i < NN) ? g_cnt[i] : 0;
    if (i < NN) g_dinv[i] = rsqrtf((float)v + 1.0f);
    sdata[t] = v;
    __syncthreads();
#pragma unroll
    for (int off = 1; off < 1024; off <<= 1) {
        int x = (t >= off) ? sdata[t - off] : 0;
        __syncthreads();
        sdata[t] += x;
        __syncthreads();
    }
    if (i < NN) {
        int excl = sdata[t] - v;
        g_rowptr[i] = excl;
        g_wptr[i]   = excl;
    }
    if (t == 1023) g_bsum[blockIdx.x] = sdata[1023];
}

// pass 2+3 fused: each block redundantly scans the 98 block sums in smem,
// then adds offsets and builds h0s = h0 * dinv. Removes the k_scan2 launch.
__global__ void k_scan3() {
    __shared__ int sdata[128];
    int t = threadIdx.x;
    if (t < 128) sdata[t] = (t < NB_SCAN) ? g_bsum[t] : 0;
    __syncthreads();
#pragma unroll
    for (int off = 1; off < 128; off <<= 1) {
        int x = 0;
        if (t < 128 && t >= off) x = sdata[t - off];
        __syncthreads();
        if (t < 128) sdata[t] += x;
        __syncthreads();
    }
    int i = blockIdx.x * blockDim.x + t;
    if (i < NN) {
        int chunk = i >> 10;
        int off = sdata[chunk] - g_bsum[chunk];  // exclusive prefix
        g_rowptr[i] += off;
        g_wptr[i]   += off;
        float dv = g_dinv[i];
#pragma unroll
        for (int c = 0; c < 16; c++)
            g_h0s[i * 16 + c] = g_h0[i * 16 + c] * dv;
    }
    if (i == 0) g_rowptr[NN] = EE;
}

__global__ void k_fill(const int* __restrict__ ei) {
    int e = blockIdx.x * blockDim.x + threadIdx.x;
    if (e < EE) {
        int s = ei[e];
        int d = ei[EE + e];
        int p = atomicAdd(&g_wptr[d], 1);
        g_colsrc[p] = s;
    }
}

// ---------------- aggregation (gather over CSR, pre-scaled inputs) ------------

// layer-0: 4 lanes per node (float4 each = 16 floats/row), unroll 4 + tail.
__global__ void k_agg16() {
    int tid = blockIdx.x * blockDim.x + threadIdx.x;
    int v = tid >> 2;
    int q = tid & 3;
    if (v >= NN) return;
    const float4* hp = (const float4*)g_h0s;   // 4 float4 per row
    float dv = g_dinv[v];
    float4 s = __ldg(hp + v * 4 + q);
    float a0 = s.x, a1 = s.y, a2 = s.z, a3 = s.w;
    int e = g_rowptr[v], end = g_rowptr[v + 1];
    for (; e + 4 <= end; e += 4) {
        int u0 = g_colsrc[e + 0];
        int u1 = g_colsrc[e + 1];
        int u2 = g_colsrc[e + 2];
        int u3 = g_colsrc[e + 3];
        float4 x0 = __ldg(hp + u0 * 4 + q);
        float4 x1 = __ldg(hp + u1 * 4 + q);
        float4 x2 = __ldg(hp + u2 * 4 + q);
        float4 x3 = __ldg(hp + u3 * 4 + q);
        a0 += (x0.x + x1.x) + (x2.x + x3.x);
        a1 += (x0.y + x1.y) + (x2.y + x3.y);
        a2 += (x0.z + x1.z) + (x2.z + x3.z);
        a3 += (x0.w + x1.w) + (x2.w + x3.w);
    }
    for (; e < end; e++) {
        int u = g_colsrc[e];
        float4 x = __ldg(hp + u * 4 + q);
        a0 += x.x; a1 += x.y; a2 += x.z; a3 += x.w;
    }
    float4 r = make_float4(a0 * dv, a1 * dv, a2 * dv, a3 * dv);
    *((float4*)g_agg16v + v * 4 + q) = r;
}

__device__ __forceinline__ void acc8(float* a, uint4 r) {
    float2 p0 = __half22float2(*(const __half2*)&r.x);
    float2 p1 = __half22float2(*(const __half2*)&r.y);
    float2 p2 = __half22float2(*(const __half2*)&r.z);
    float2 p3 = __half22float2(*(const __half2*)&r.w);
    a[0] += p0.x; a[1] += p0.y; a[2] += p1.x; a[3] += p1.y;
    a[4] += p2.x; a[5] += p2.y; a[6] += p3.x; a[7] += p3.y;
}

// 128-channel: 16 lanes per node (2 nodes/warp), uint4 = 8 halves per lane.
__global__ void __launch_bounds__(256) k_agg128() {
    int tid = blockIdx.x * blockDim.x + threadIdx.x;
    int node = tid >> 4;
    if (node >= NN) return;
    int lane = threadIdx.x & 15;
    const uint4* hp = (const uint4*)g_hs;   // 16 uint4 per 128-half row
    float dv = g_dinv[node];
    float a[8] = {0.f, 0.f, 0.f, 0.f, 0.f, 0.f, 0.f, 0.f};
    acc8(a, __ldg(hp + node * 16 + lane));  // self term
    int e = g_rowptr[node], end = g_rowptr[node + 1];
    for (; e + 4 <= end; e += 4) {
        int u0 = g_colsrc[e + 0];
        int u1 = g_colsrc[e + 1];
        int u2 = g_colsrc[e + 2];
        int u3 = g_colsrc[e + 3];
        uint4 r0 = __ldg(hp + u0 * 16 + lane);
        uint4 r1 = __ldg(hp + u1 * 16 + lane);
        uint4 r2 = __ldg(hp + u2 * 16 + lane);
        uint4 r3 = __ldg(hp + u3 * 16 + lane);
        acc8(a, r0); acc8(a, r1); acc8(a, r2); acc8(a, r3);
    }
    for (; e < end; e++) {
        int u = g_colsrc[e];
        acc8(a, __ldg(hp + u * 16 + lane));
    }
    __half2 h0 = __floats2half2_rn(a[0] * dv, a[1] * dv);
    __half2 h1 = __floats2half2_rn(a[2] * dv, a[3] * dv);
    __half2 h2 = __floats2half2_rn(a[4] * dv, a[5] * dv);
    __half2 h3 = __floats2half2_rn(a[6] * dv, a[7] * dv);
    uint4 ov;
    ov.x = *(const unsigned int*)&h0;
    ov.y = *(const unsigned int*)&h1;
    ov.z = *(const unsigned int*)&h2;
    ov.w = *(const unsigned int*)&h3;
    *((uint4*)g_aggh + node * 16 + lane) = ov;
}

// ---------------- GEMMs -------------------------------------------------------

// layer-0 GEMM: [N,16] @ [16,128] + b -> hs(fp16) = relu(out)*dinv
__global__ void k_gemm0(const float* __restrict__ W0, const float* __restrict__ b0) {
    __shared__ float Ws[16 * 128];
    int t = threadIdx.x;
    for (int i = t; i < 16 * 128; i += 256) Ws[i] = W0[i];
    __syncthreads();
    int row = blockIdx.x * 2 + (t >> 7);
    int col = t & 127;
    float acc = b0[col];
#pragma unroll
    for (int k = 0; k < 16; k++)
        acc += g_agg16v[row * 16 + k] * Ws[k * 128 + col];
    g_hs[row * HID + col] = __float2half(fmaxf(acc, 0.f) * g_dinv[row]);
}

// single-MMA fp16 tensor-core GEMM: [N,128] @ [128,128] + b
// W double-buffered in smem -> one __syncthreads per k-chunk.
// emode: 0 = raw fp32 out, 2 = relu*dinv -> fp16 hs buffer,
//        3 = fused head: t=relu(.) into smem, then pred = t @ Wr2 + br2
#define H_LD 136
#define H_SMEM (128 * H_LD * 2 + 2 * 32 * H_LD * 2 + 8 * 256 * 4 + 128 * 3 * 4)

__global__ void __launch_bounds__(256)
k_gemm16(const __half* __restrict__ in_h, const float* __restrict__ in_f,
         int widx, const float* __restrict__ bias,
         float* __restrict__ out_f, __half* __restrict__ out_h, int emode,
         const float* __restrict__ Wr2, const float* __restrict__ br2,
         float* __restrict__ out_pred) {
    extern __shared__ char sraw[];
    __half* As = (__half*)sraw;                 // 128 x H_LD
    __half* Wsm = As + 128 * H_LD;              // 2 x 32 x H_LD (double buffer)
    float* scratch = (float*)(Wsm + 2 * 32 * H_LD); // 8 x 256
    float* wr2s = scratch + 8 * 256;            // 128 x 3

    int t = threadIdx.x;
    int warp = t >> 5;
    int lane = t & 31;
    int warp_r = warp & 3;
    int warp_c = warp >> 2;
    int row0 = blockIdx.x * 128;
    bool full = (row0 + 128 <= NN);

    const __half* W = g_wh + widx * 128 * 128;

    uint4 vw[2];
    auto load_w = [&](int kc) {
#pragma unroll
        for (int l = 0; l < 2; l++) {
            int idx = t + l * 256;
            int kr = idx >> 4, q = idx & 15;
            vw[l] = __ldg((const uint4*)(W + (kc + kr) * 128 + q * 8));
        }
    };
    auto store_w = [&](int buf) {
        __half* dst = Wsm + buf * 32 * H_LD;
#pragma unroll
        for (int l = 0; l < 2; l++) {
            int idx = t + l * 256;
            int kr = idx >> 4, q = idx & 15;
            *(uint4*)(&dst[kr * H_LD + q * 8]) = vw[l];
        }
    };

    load_w(0);

    // ---- load full A tile (128 x 128 halves) ----
    if (in_h) {
#pragma unroll
        for (int l = 0; l < 8; l++) {
            int idx = t + l * 256;
            int r = idx >> 4, q = idx & 15;
            int gr = row0 + r;
            uint4 v = make_uint4(0, 0, 0, 0);
            if (gr < NN) v = __ldg((const uint4*)(in_h + gr * HID + q * 8));
            *(uint4*)(&As[r * H_LD + q * 8]) = v;
        }
    } else {
        // fp32 input with relu (head path)
#pragma unroll
        for (int l = 0; l < 16; l++) {
            int idx = t + l * 256;
            int r = idx >> 5, q = idx & 31;
            int gr = row0 + r;
            float4 v = make_float4(0.f, 0.f, 0.f, 0.f);
            if (gr < NN) v = __ldg((const float4*)(in_f + gr * HID + q * 4));
            __half2 p0 = __floats2half2_rn(fmaxf(v.x, 0.f), fmaxf(v.y, 0.f));
            __half2 p1 = __floats2half2_rn(fmaxf(v.z, 0.f), fmaxf(v.w, 0.f));
            *(__half2*)(&As[r * H_LD + q * 4])     = p0;
            *(__half2*)(&As[r * H_LD + q * 4 + 2]) = p1;
        }
    }
    store_w(0);
    if (emode == 3) {
        for (int i = t; i < 384; i += 256) wr2s[i] = __ldg(&Wr2[i]);
    }
    __syncthreads();

    // ---- MMA phase ----
    wmma::fragment<wmma::accumulator, 16, 16, 16, float> acc[2][4];
#pragma unroll
    for (int i = 0; i < 2; i++)
#pragma unroll
        for (int j = 0; j < 4; j++) wmma::fill_fragment(acc[i][j], 0.0f);

    for (int chunk = 0; chunk < 4; chunk++) {
        if (chunk < 3) load_w((chunk + 1) * 32);
        const __half* Wb = Wsm + (chunk & 1) * 32 * H_LD;
#pragma unroll
        for (int ks = 0; ks < 2; ks++) {
            int ka = chunk * 32 + ks * 16;
            wmma::fragment<wmma::matrix_a, 16, 16, 16, __half, wmma::row_major> af[2];
            wmma::fragment<wmma::matrix_b, 16, 16, 16, __half, wmma::row_major> bf[4];
#pragma unroll
            for (int i = 0; i < 2; i++)
                wmma::load_matrix_sync(af[i], &As[(warp_r * 32 + i * 16) * H_LD + ka], H_LD);
#pragma unroll
            for (int j = 0; j < 4; j++)
                wmma::load_matrix_sync(bf[j], &Wb[(ks * 16) * H_LD + warp_c * 64 + j * 16], H_LD);
#pragma unroll
            for (int i = 0; i < 2; i++)
#pragma unroll
                for (int j = 0; j < 4; j++)
                    wmma::mma_sync(acc[i][j], af[i], bf[j], acc[i][j]);
        }
        if (chunk < 3) {
            store_w((chunk + 1) & 1);
            __syncthreads();
        }
    }

    if (emode == 3) __syncthreads();  // MMA reads of As done before t writes

    // ---- epilogue ----
    float* sc = &scratch[warp * 256];
#pragma unroll
    for (int i = 0; i < 2; i++)
#pragma unroll
        for (int j = 0; j < 4; j++) {
            wmma::store_matrix_sync(sc, acc[i][j], 16, wmma::mem_row_major);
            __syncwarp();
#pragma unroll
            for (int e = 0; e < 8; e++) {
                int idx = lane + e * 32;
                int r = idx >> 4, c = idx & 15;
                int rl = warp_r * 32 + i * 16 + r;
                int gr = row0 + rl;
                int gc = warp_c * 64 + j * 16 + c;
                if (full || gr < NN) {
                    float v = sc[idx] + __ldg(&bias[gc]);
                    if (emode == 2) {
                        v = fmaxf(v, 0.f) * __ldg(&g_dinv[gr]);
                        out_h[gr * HID + gc] = __float2half(v);
                    } else if (emode == 3) {
                        As[rl * H_LD + gc] = __float2half(fmaxf(v, 0.f));
                    } else {
                        out_f[gr * HID + gc] = v;
                    }
                }
            }
            __syncwarp();
        }

    // ---- fused pred head (emode 3): pred = t @ Wr2 + br2 ----
    if (emode == 3) {
        __syncthreads();  // t tile complete in As
        int row = t >> 1;
        int half_id = t & 1;
        int k0 = half_id * 64;
        float p0 = 0.f, p1 = 0.f, p2 = 0.f;
#pragma unroll
        for (int k = 0; k < 64; k += 2) {
            __half2 hv = *(__half2*)(&As[row * H_LD + k0 + k]);
            float2 f = __half22float2(hv);
            const float* w0 = &wr2s[(k0 + k) * 3];
            p0 += f.x * w0[0] + f.y * w0[3];
            p1 += f.x * w0[1] + f.y * w0[4];
            p2 += f.x * w0[2] + f.y * w0[5];
        }
        p0 += __shfl_xor_sync(0xFFFFFFFF, p0, 1);
        p1 += __shfl_xor_sync(0xFFFFFFFF, p1, 1);
        p2 += __shfl_xor_sync(0xFFFFFFFF, p2, 1);
        int gr = row0 + row;
        if (half_id == 0 && gr < NN) {
            out_pred[gr * 3 + 0] = p0 + __ldg(&br2[0]);
            out_pred[gr * 3 + 1] = p1 + __ldg(&br2[1]);
            out_pred[gr * 3 + 2] = p2 + __ldg(&br2[2]);
        }
    }
}

// ---------------- launch ------------------------------------------------------

extern "C" void kernel_launch(void* const* d_in, const int* in_sizes, int n_in,
                              void* d_out, int out_size) {
    const float* x    = (const float*)d_in[0];
    const float* xm   = (const float*)d_in[1];
    const int*   ei   = (const int*)d_in[2];
    const float* W0   = (const float*)d_in[3];
    const float* b0   = (const float*)d_in[4];
    const float* Wh   = (const float*)d_in[5];
    const float* bh   = (const float*)d_in[6];
    const float* Wr1  = (const float*)d_in[7];
    const float* br1  = (const float*)d_in[8];
    const float* Wr2  = (const float*)d_in[9];
    const float* br2  = (const float*)d_in[10];
    float* out = (float*)d_out;
    float* out_emb  = out;             // [N,128]
    float* out_pred = out + NN * HID;  // [N,3]

    __half* p_aggh; cudaGetSymbolAddress((void**)&p_aggh, g_aggh);
    __half* p_hs;   cudaGetSymbolAddress((void**)&p_hs,   g_hs);

    static int smem_set = 0;
    if (!smem_set) {
        cudaFuncSetAttribute(k_gemm16, cudaFuncAttributeMaxDynamicSharedMemorySize,
                             H_SMEM);
        smem_set = 1;
    }

    // graph preprocessing (init + weight conversion fused); grid covers
    // max(NN, 5*128*128) — all NN node clears required for graph replay.
    int initw_threads = (NN > 5 * 128 * 128) ? NN : 5 * 128 * 128;
    k_initw<<<(initw_threads + 255) / 256, 256>>>(x, xm, Wh, Wr1);
    k_count<<<(EE + 255) / 256, 256>>>(ei);
    k_scan1<<<NB_SCAN, 1024>>>();
    k_scan3<<<(NN + 255) / 256, 256>>>();   // fused scan2+scan3
    k_fill<<<(EE + 255) / 256, 256>>>(ei);

    int gemm_blocks = (NN + 127) / 128;

    // layer 0: aggregate 16-dim (4 lanes/node), then GEMM to 128
    k_agg16<<<(NN * 4 + 255) / 256, 256>>>();
    k_gemm0<<<NN / 2, 256>>>(W0, b0);

    // hidden layers 0..3
    for (int i = 0; i < 4; i++) {
        k_agg128<<<(NN * 16 + 255) / 256, 256>>>();
        if (i == 3)
            k_gemm16<<<gemm_blocks, 256, H_SMEM>>>(p_aggh, nullptr, i, bh + i * 128,
                                                   out_emb, nullptr, 0,
                                                   nullptr, nullptr, nullptr);
        else
            k_gemm16<<<gemm_blocks, 256, H_SMEM>>>(p_aggh, nullptr, i, bh + i * 128,
                                                   nullptr, p_hs, 2,
                                                   nullptr, nullptr, nullptr);
    }

    // fused head: t = relu(relu(emb) @ Wr1 + br1); pred = t @ Wr2 + br2
    k_gemm16<<<gemm_blocks, 256, H_SMEM>>>(nullptr, out_emb, 4, br1,
                                           nullptr, nullptr, 3,
                                           Wr2, br2, out_pred);
}